// round 14
// baseline (speedup 1.0000x reference)
#include <cuda_runtime.h>
#include <cuda_bf16.h>
#include <math.h>

// ---------------------------------------------------------------------------
// SMPL LBS point deformer — wide prep + heavy pass (4 points/thread).
// Inputs (metadata order):
//  0 points      (3, N)        float32
//  1 weights     (24, N)       float32
//  2 beta        (10,)         float32
//  3 theta       (24, 3)       float32
//  4 da_theta    (24, 3)       float32
//  5 shapedirs   (NV, 3, 10)   float32
//  6 v_template  (NV, 3)       float32
//  7 J_regressor (24, NV)      float32
// Output: (1, 3, N) float32
//
// Identities used:
//   J_pose = Jreg@v_template + (Jreg@shapedirs)@beta ; J_da = Jreg@v_template
//   sum_j w_j = 1  =>  v = A23*p + sum_{j<23} w_j (A_j - A23) * p
// ---------------------------------------------------------------------------

#define NJ 24
#define NSPLIT 32         // v-dimension splits per joint -> grid = 24*32 = 768
#define NACC 33           // 3 template dots + 30 shapedir dots

__constant__ int c_par[NJ] = {-1,0,0,0,1,2,3,4,5,6,7,8,9,9,9,12,13,14,16,17,18,19,20,21};

__device__ float g_partial[NJ * NSPLIT * NACC];
__device__ float g_A[NJ * 12];                    // float A (scalar fallback)
__device__ unsigned long long g_Dpk[23 * 12];     // {d,d} packed, d=A_j-A_23
__device__ unsigned long long g_A23pk[12];        // {a,a} packed, a=A_23
__device__ int   g_ctr;                           // finisher resets each run

// 3x4 rigid compose: G_out = G_parent ∘ L
__device__ __forceinline__ void compose(const float* Gp, const float* Lj,
                                        float* Go) {
    float T[12];
#pragma unroll
    for (int r = 0; r < 3; r++) {
#pragma unroll
        for (int c = 0; c < 3; c++)
            T[r * 3 + c] = Gp[r * 3 + 0] * Lj[0 * 3 + c] +
                           Gp[r * 3 + 1] * Lj[1 * 3 + c] +
                           Gp[r * 3 + 2] * Lj[2 * 3 + c];
        T[9 + r] = Gp[r * 3 + 0] * Lj[9] + Gp[r * 3 + 1] * Lj[10] +
                   Gp[r * 3 + 2] * Lj[11] + Gp[9 + r];
    }
#pragma unroll
    for (int k = 0; k < 12; k++) Go[k] = T[k];
}

// product of locals along the ancestor path root->jj
__device__ __forceinline__ void chain(const float (*L)[12], int jj, float* G) {
    int path[10];
    int d = 0, p = jj;
    while (p >= 0) { path[d++] = p; p = c_par[p]; }
    const float* L0 = L[path[d - 1]];       // root
#pragma unroll
    for (int k = 0; k < 12; k++) G[k] = L0[k];
    for (int k = d - 2; k >= 0; k--) compose(G, L[path[k]], G);
}

// ---------------------------------------------------------------------------
// Kernel 1: grid (NJ*NSPLIT) blocks, 256 threads, ONE vertex per thread.
// Last-finishing block reduces partials, builds A, packs deltas, triggers.
// ---------------------------------------------------------------------------
__global__ void __launch_bounds__(256) k_prep(
    const float* __restrict__ Jreg,
    const float* __restrict__ v_template,
    const float* __restrict__ shapedirs,
    const float* __restrict__ beta,
    const float* __restrict__ theta,
    const float* __restrict__ da_theta,
    int nv) {
    const int bx  = blockIdx.x;
    const int j   = bx / NSPLIT;
    const int sp  = bx % NSPLIT;
    const int tid = threadIdx.x;
    const int chunk = (nv + NSPLIT - 1) / NSPLIT;
    const int v0 = sp * chunk;
    const int v1 = min(nv, v0 + chunk);
    const int v  = v0 + tid;

    float acc[NACC];
#pragma unroll
    for (int k = 0; k < NACC; k++) acc[k] = 0.f;

    if (v < v1) {
        float w = Jreg[(size_t)j * nv + v];
        acc[0] = w * v_template[v * 3 + 0];
        acc[1] = w * v_template[v * 3 + 1];
        acc[2] = w * v_template[v * 3 + 2];
        const float* sd = shapedirs + (size_t)v * 30;
#pragma unroll
        for (int m = 0; m < 30; m++) acc[3 + m] = w * sd[m];
    }

    __shared__ float red[8][NACC];
    int lane = tid & 31, warp = tid >> 5;
#pragma unroll
    for (int k = 0; k < NACC; k++) {
        float x = acc[k];
#pragma unroll
        for (int off = 16; off > 0; off >>= 1)
            x += __shfl_down_sync(0xffffffffu, x, off);
        if (lane == 0) red[warp][k] = x;
    }
    __syncthreads();
    if (tid < NACC) {
        float s = 0.f;
#pragma unroll
        for (int w = 0; w < 8; w++) s += red[w][tid];
        g_partial[bx * NACC + tid] = s;
    }
    __syncthreads();

    __shared__ int s_last;
    if (tid == 0) {
        __threadfence();
        s_last = (atomicAdd(&g_ctr, 1) == NJ * NSPLIT - 1);
    }
    __syncthreads();
    if (!s_last) {
        cudaTriggerProgrammaticLaunchCompletion();
        return;
    }
    __threadfence();

    // ---------------- finisher: reduce partials, build A ----------------
    __shared__ float sP[NJ][NACC];
    for (int i = tid; i < NJ * NACC; i += 256) {
        int jj = i / NACC, c = i % NACC;
        float s = 0.f;
#pragma unroll
        for (int sp2 = 0; sp2 < NSPLIT; sp2++)
            s += __ldcg(&g_partial[(jj * NSPLIT + sp2) * NACC + c]);
        sP[jj][c] = s;
    }
    __syncthreads();

    __shared__ float sJ[2][NJ * 3];    // [0]=pose, [1]=da
    if (tid < NJ) {
        int jj = tid;
        float b[10];
#pragma unroll
        for (int k = 0; k < 10; k++) b[k] = __ldg(&beta[k]);
#pragma unroll
        for (int c = 0; c < 3; c++) {
            float jd = sP[jj][c];
            float jp = jd;
#pragma unroll
            for (int k = 0; k < 10; k++) jp += sP[jj][3 + c * 10 + k] * b[k];
            sJ[0][jj * 3 + c] = jp;
            sJ[1][jj * 3 + c] = jd;
        }
    }
    __syncthreads();

    __shared__ float L[2][NJ][12];
    if (tid < 48) {
        int s = tid / NJ;          // 0 = pose, 1 = da
        int jj = tid % NJ;
        const float* th = (s == 0 ? theta : da_theta) + jj * 3;
        float rx = th[0], ry = th[1], rz = th[2];
        float nrm = sqrtf(rx * rx + ry * ry + rz * rz) + 1e-8f;
        float x = rx / nrm, y = ry / nrm, z = rz / nrm;
        float c = cosf(nrm), sn = sinf(nrm), ic = 1.0f - c;
        float* Lj = L[s][jj];
        Lj[0] = c + ic * x * x;      Lj[1] = ic * x * y - sn * z;  Lj[2] = ic * x * z + sn * y;
        Lj[3] = ic * x * y + sn * z; Lj[4] = c + ic * y * y;       Lj[5] = ic * y * z - sn * x;
        Lj[6] = ic * x * z - sn * y; Lj[7] = ic * y * z + sn * x;  Lj[8] = c + ic * z * z;
        const float* J = sJ[s];
        int p = c_par[jj];
        if (p < 0) {
            Lj[9] = J[0]; Lj[10] = J[1]; Lj[11] = J[2];
        } else {
            Lj[9]  = J[jj * 3 + 0] - J[p * 3 + 0];
            Lj[10] = J[jj * 3 + 1] - J[p * 3 + 1];
            Lj[11] = J[jj * 3 + 2] - J[p * 3 + 2];
        }
    }
    __syncthreads();

    // per-joint ancestor-path chains (pose+da in one thread), pack, A
    __shared__ float sAf[NJ][12];
    if (tid < NJ) {
        int jj = tid;
        float P[12], D[12];
        chain(L[0], jj, P);
        chain(L[1], jj, D);
        // pack: t -= R @ J_rest
#pragma unroll
        for (int rr = 0; rr < 3; rr++) {
            P[9 + rr] -= P[rr * 3 + 0] * sJ[0][jj * 3 + 0] +
                         P[rr * 3 + 1] * sJ[0][jj * 3 + 1] +
                         P[rr * 3 + 2] * sJ[0][jj * 3 + 2];
            D[9 + rr] -= D[rr * 3 + 0] * sJ[1][jj * 3 + 0] +
                         D[rr * 3 + 1] * sJ[1][jj * 3 + 1] +
                         D[rr * 3 + 2] * sJ[1][jj * 3 + 2];
        }
        // A = P ∘ rigid_inverse(D)
        float ti[3];
#pragma unroll
        for (int rr = 0; rr < 3; rr++)
            ti[rr] = -(D[0 * 3 + rr] * D[9] + D[1 * 3 + rr] * D[10] +
                       D[2 * 3 + rr] * D[11]);
#pragma unroll
        for (int rr = 0; rr < 3; rr++) {
#pragma unroll
            for (int cc = 0; cc < 3; cc++)
                sAf[jj][rr * 4 + cc] = P[rr * 3 + 0] * D[cc * 3 + 0] +
                                       P[rr * 3 + 1] * D[cc * 3 + 1] +
                                       P[rr * 3 + 2] * D[cc * 3 + 2];
            sAf[jj][rr * 4 + 3] = P[rr * 3 + 0] * ti[0] + P[rr * 3 + 1] * ti[1] +
                                  P[rr * 3 + 2] * ti[2] + P[9 + rr];
        }
    }
    __syncthreads();

    // publish: float A + packed deltas
    for (int i = tid; i < NJ * 12; i += 256) {
        int jj = i / 12, k = i % 12;
        float a = sAf[jj][k];
        g_A[i] = a;
        if (jj < 23) {
            float d = a - sAf[23][k];
            unsigned long long u = (unsigned long long)__float_as_uint(d);
            g_Dpk[i] = u | (u << 32);
        } else {
            unsigned long long u = (unsigned long long)__float_as_uint(a);
            g_A23pk[k] = u | (u << 32);
        }
    }
    __syncthreads();
    if (tid == 0) {
        g_ctr = 0;          // reset for next replay (deterministic)
        __threadfence();    // publish before releasing dependents
    }
    __syncthreads();
    cudaTriggerProgrammaticLaunchCompletion();
}

// ---------------------------------------------------------------------------
// Kernel 2: heavy per-point pass — 4 points/thread (measured-best shape:
// 16B loads, 64 regs, occ 4 blocks/SM). v = A23*p + sum_{j<23} w_j (Aj-A23)*p
// ---------------------------------------------------------------------------
__device__ __forceinline__ unsigned long long fma2(unsigned long long a,
                                                   unsigned long long b,
                                                   unsigned long long c) {
    unsigned long long d;
    asm("fma.rn.f32x2 %0, %1, %2, %3;" : "=l"(d) : "l"(a), "l"(b), "l"(c));
    return d;
}

__device__ __forceinline__ unsigned long long add2(unsigned long long a,
                                                   unsigned long long b) {
    unsigned long long d;
    asm("add.rn.f32x2 %0, %1, %2;" : "=l"(d) : "l"(a), "l"(b));
    return d;
}

__device__ __forceinline__ ulonglong2 ldcs2(const ulonglong2* p) {
    ulonglong2 v;
    asm("ld.global.cs.v2.u64 {%0, %1}, [%2];"
        : "=l"(v.x), "=l"(v.y) : "l"(p));
    return v;
}

__device__ __forceinline__ void stcs2(ulonglong2* p, ulonglong2 v) {
    asm("st.global.cs.v2.u64 [%0], {%1, %2};" :: "l"(p), "l"(v.x), "l"(v.y)
        : "memory");
}

__global__ void __launch_bounds__(256, 4) k_lbs_vec(
    const float* __restrict__ points, const float* __restrict__ weights,
    float* __restrict__ out, int N, long long nGroups) {
    long long g = (long long)blockIdx.x * blockDim.x + threadIdx.x;
    bool act = (g < nGroups);
    long long gc = act ? g : 0;

    // Point loads don't depend on A — issue before the grid sync.
    ulonglong2 X, Y, Z;
    if (act) {
        X = ldcs2(reinterpret_cast<const ulonglong2*>(points) + gc);
        Y = ldcs2(reinterpret_cast<const ulonglong2*>(points + (size_t)N) + gc);
        Z = ldcs2(reinterpret_cast<const ulonglong2*>(points + 2 * (size_t)N) + gc);
    }

    cudaGridDependencySynchronize();

    __shared__ __align__(16) unsigned long long sD[23 * 12];
    __shared__ __align__(16) unsigned long long sA23[12];
    for (int i = threadIdx.x; i < 23 * 12 + 12; i += blockDim.x) {
        if (i < 23 * 12) sD[i] = __ldcg(&g_Dpk[i]);
        else             sA23[i - 23 * 12] = __ldcg(&g_A23pk[i - 23 * 12]);
    }
    __syncthreads();
    if (!act) return;

    unsigned long long vxa = 0ull, vya = 0ull, vza = 0ull;
    unsigned long long vxb = 0ull, vyb = 0ull, vzb = 0ull;

#pragma unroll
    for (int j = 0; j < 23; j++) {
        const ulonglong2 W =
            ldcs2(reinterpret_cast<const ulonglong2*>(weights + (size_t)j * N) + g);
        const ulonglong2* ap = reinterpret_cast<const ulonglong2*>(&sD[j * 12]);
        const ulonglong2 a01 = ap[0], a23_ = ap[1], a45 = ap[2];
        const ulonglong2 a67 = ap[3], a89 = ap[4], aAB = ap[5];
        unsigned long long s;
        // pair a (points 4g, 4g+1)
        s = fma2(a01.x, X.x, a23_.y); s = fma2(a01.y, Y.x, s); s = fma2(a23_.x, Z.x, s); vxa = fma2(W.x, s, vxa);
        s = fma2(a45.x, X.x, a67.y);  s = fma2(a45.y, Y.x, s); s = fma2(a67.x,  Z.x, s); vya = fma2(W.x, s, vya);
        s = fma2(a89.x, X.x, aAB.y);  s = fma2(a89.y, Y.x, s); s = fma2(aAB.x,  Z.x, s); vza = fma2(W.x, s, vza);
        // pair b (points 4g+2, 4g+3)
        s = fma2(a01.x, X.y, a23_.y); s = fma2(a01.y, Y.y, s); s = fma2(a23_.x, Z.y, s); vxb = fma2(W.y, s, vxb);
        s = fma2(a45.x, X.y, a67.y);  s = fma2(a45.y, Y.y, s); s = fma2(a67.x,  Z.y, s); vyb = fma2(W.y, s, vyb);
        s = fma2(a89.x, X.y, aAB.y);  s = fma2(a89.y, Y.y, s); s = fma2(aAB.x,  Z.y, s); vzb = fma2(W.y, s, vzb);
    }

    // epilogue: + A23 * p
    {
        const ulonglong2* ap = reinterpret_cast<const ulonglong2*>(sA23);
        const ulonglong2 a01 = ap[0], a23_ = ap[1], a45 = ap[2];
        const ulonglong2 a67 = ap[3], a89 = ap[4], aAB = ap[5];
        unsigned long long s;
        s = fma2(a01.x, X.x, a23_.y); s = fma2(a01.y, Y.x, s); s = fma2(a23_.x, Z.x, s); vxa = add2(vxa, s);
        s = fma2(a45.x, X.x, a67.y);  s = fma2(a45.y, Y.x, s); s = fma2(a67.x,  Z.x, s); vya = add2(vya, s);
        s = fma2(a89.x, X.x, aAB.y);  s = fma2(a89.y, Y.x, s); s = fma2(aAB.x,  Z.x, s); vza = add2(vza, s);
        s = fma2(a01.x, X.y, a23_.y); s = fma2(a01.y, Y.y, s); s = fma2(a23_.x, Z.y, s); vxb = add2(vxb, s);
        s = fma2(a45.x, X.y, a67.y);  s = fma2(a45.y, Y.y, s); s = fma2(a67.x,  Z.y, s); vyb = add2(vyb, s);
        s = fma2(a89.x, X.y, aAB.y);  s = fma2(a89.y, Y.y, s); s = fma2(aAB.x,  Z.y, s); vzb = add2(vzb, s);
    }

    ulonglong2 o;
    o.x = vxa; o.y = vxb; stcs2(reinterpret_cast<ulonglong2*>(out) + g, o);
    o.x = vya; o.y = vyb; stcs2(reinterpret_cast<ulonglong2*>(out + (size_t)N) + g, o);
    o.x = vza; o.y = vzb; stcs2(reinterpret_cast<ulonglong2*>(out + 2 * (size_t)N) + g, o);
}

// Scalar fallback (only used if N % 4 != 0 — not the case for this problem).
__global__ void k_lbs_scalar(const float* __restrict__ points,
                             const float* __restrict__ weights,
                             float* __restrict__ out, int N) {
    __shared__ float sA[NJ * 12];
    for (int i = threadIdx.x; i < NJ * 12; i += blockDim.x) sA[i] = __ldcg(&g_A[i]);
    __syncthreads();
    long long n = (long long)blockIdx.x * blockDim.x + threadIdx.x;
    if (n >= N) return;
    float px = points[n], py = points[(size_t)N + n], pz = points[2 * (size_t)N + n];
    float vx = 0.f, vy = 0.f, vz = 0.f;
#pragma unroll
    for (int j = 0; j < NJ; j++) {
        float w = weights[(size_t)j * N + n];
        const float* a = &sA[j * 12];
        vx += w * (a[0] * px + a[1] * py + a[2]  * pz + a[3]);
        vy += w * (a[4] * px + a[5] * py + a[6]  * pz + a[7]);
        vz += w * (a[8] * px + a[9] * py + a[10] * pz + a[11]);
    }
    out[n] = vx; out[(size_t)N + n] = vy; out[2 * (size_t)N + n] = vz;
}

// ---------------------------------------------------------------------------
extern "C" void kernel_launch(void* const* d_in, const int* in_sizes, int n_in,
                              void* d_out, int out_size) {
    const float* points      = (const float*)d_in[0];
    const float* weights     = (const float*)d_in[1];
    const float* beta        = (const float*)d_in[2];
    const float* theta       = (const float*)d_in[3];
    const float* da_theta    = (const float*)d_in[4];
    const float* shapedirs   = (const float*)d_in[5];
    const float* v_template  = (const float*)d_in[6];
    const float* J_regressor = (const float*)d_in[7];

    int N  = in_sizes[0] / 3;          // number of points
    int NV = in_sizes[5] / 30;         // template vertex count

    // wide prep (grid 768, 1 vertex/thread): partials + finisher transforms
    k_prep<<<NJ * NSPLIT, 256>>>(J_regressor, v_template, shapedirs, beta,
                                 theta, da_theta, NV);

    if ((N & 3) == 0) {
        long long nGroups = (long long)N / 4;
        int blocks = (int)((nGroups + 255) / 256);

        cudaLaunchConfig_t cfg = {};
        cfg.gridDim  = dim3((unsigned)blocks, 1, 1);
        cfg.blockDim = dim3(256, 1, 1);
        cfg.dynamicSmemBytes = 0;
        cudaLaunchAttribute attrs[1];
        attrs[0].id = cudaLaunchAttributeProgrammaticStreamSerialization;
        attrs[0].val.programmaticStreamSerializationAllowed = 1;
        cfg.attrs = attrs;
        cfg.numAttrs = 1;
        cudaError_t err = cudaLaunchKernelEx(&cfg, k_lbs_vec,
                                             points, weights, (float*)d_out,
                                             N, nGroups);
        if (err != cudaSuccess) {
            k_lbs_vec<<<blocks, 256>>>(points, weights, (float*)d_out, N, nGroups);
        }
    } else {
        int blocks = (N + 255) / 256;
        k_lbs_scalar<<<blocks, 256>>>(points, weights, (float*)d_out, N);
    }
}

// round 15
// speedup vs baseline: 1.2823x; 1.2823x over previous
#include <cuda_runtime.h>
#include <cuda_bf16.h>
#include <math.h>

// ---------------------------------------------------------------------------
// SMPL LBS point deformer — SINGLE fused kernel (prep in first wave + LBS).
// Inputs (metadata order):
//  0 points      (3, N)        float32
//  1 weights     (24, N)       float32
//  2 beta        (10,)         float32
//  3 theta       (24, 3)       float32
//  4 da_theta    (24, 3)       float32
//  5 shapedirs   (NV, 3, 10)   float32
//  6 v_template  (NV, 3)       float32
//  7 J_regressor (24, NV)      float32
// Output: (1, 3, N) float32
//
// Identities: J_pose = Jreg@v_template + (Jreg@shapedirs)@beta ; J_da = Jreg@v_template
//             sum_j w_j = 1  =>  v = A23*p + sum_{j<23} w_j (A_j - A23) * p
//
// Safety: prep spans NJ*NSPLIT = 576 blocks <= 592 = guaranteed first-wave
// residency (148 SMs x occ 4 at 64 regs), so the flag-wait cannot deadlock.
// ---------------------------------------------------------------------------

#define NJ 24
#define NSPLIT 24         // prep blocks = 24*24 = 576 <= 592 first-wave
#define NACC 33           // 3 template dots + 30 shapedir dots

__constant__ int c_par[NJ] = {-1,0,0,0,1,2,3,4,5,6,7,8,9,9,9,12,13,14,16,17,18,19,20,21};

__device__ float g_partial[NJ * NSPLIT * NACC];
__device__ float g_A[NJ * 12];                    // float A (scalar fallback)
__device__ unsigned long long g_Dpk[23 * 12];     // {d,d} packed, d=A_j-A_23
__device__ unsigned long long g_A23pk[12];        // {a,a} packed, a=A_23
__device__ int   g_ctr;                           // prep blocks done
__device__ int   g_done;                          // all blocks done (reset)
__device__ int   g_flag;                          // A published

// 3x4 rigid compose: G_out = G_parent ∘ L
__device__ __forceinline__ void compose(const float* Gp, const float* Lj,
                                        float* Go) {
    float T[12];
#pragma unroll
    for (int r = 0; r < 3; r++) {
#pragma unroll
        for (int c = 0; c < 3; c++)
            T[r * 3 + c] = Gp[r * 3 + 0] * Lj[0 * 3 + c] +
                           Gp[r * 3 + 1] * Lj[1 * 3 + c] +
                           Gp[r * 3 + 2] * Lj[2 * 3 + c];
        T[9 + r] = Gp[r * 3 + 0] * Lj[9] + Gp[r * 3 + 1] * Lj[10] +
                   Gp[r * 3 + 2] * Lj[11] + Gp[9 + r];
    }
#pragma unroll
    for (int k = 0; k < 12; k++) Go[k] = T[k];
}

// product of locals along the ancestor path root->jj
__device__ __forceinline__ void chain(const float (*L)[12], int jj, float* G) {
    int path[10];
    int d = 0, p = jj;
    while (p >= 0) { path[d++] = p; p = c_par[p]; }
    const float* L0 = L[path[d - 1]];
#pragma unroll
    for (int k = 0; k < 12; k++) G[k] = L0[k];
    for (int k = d - 2; k >= 0; k--) compose(G, L[path[k]], G);
}

__device__ __forceinline__ unsigned long long fma2(unsigned long long a,
                                                   unsigned long long b,
                                                   unsigned long long c) {
    unsigned long long d;
    asm("fma.rn.f32x2 %0, %1, %2, %3;" : "=l"(d) : "l"(a), "l"(b), "l"(c));
    return d;
}

__device__ __forceinline__ unsigned long long add2(unsigned long long a,
                                                   unsigned long long b) {
    unsigned long long d;
    asm("add.rn.f32x2 %0, %1, %2;" : "=l"(d) : "l"(a), "l"(b));
    return d;
}

__device__ __forceinline__ ulonglong2 ldcs2(const ulonglong2* p) {
    ulonglong2 v;
    asm("ld.global.cs.v2.u64 {%0, %1}, [%2];"
        : "=l"(v.x), "=l"(v.y) : "l"(p));
    return v;
}

__device__ __forceinline__ void stcs2(ulonglong2* p, ulonglong2 v) {
    asm("st.global.cs.v2.u64 [%0], {%1, %2};" :: "l"(p), "l"(v.x), "l"(v.y)
        : "memory");
}

// ---------------------------------------------------------------------------
// THE fused kernel. Blocks [0,576): prep partials; last-to-finish builds A,
// publishes flag. ALL blocks: wait flag (one L2 poll + nanosleep), then
// one-shot 4-points/thread LBS. Last block to finish resets state.
// ---------------------------------------------------------------------------
__global__ void __launch_bounds__(256, 4) k_all(
    const float* __restrict__ points,
    const float* __restrict__ weights,
    const float* __restrict__ beta,
    const float* __restrict__ theta,
    const float* __restrict__ da_theta,
    const float* __restrict__ shapedirs,
    const float* __restrict__ v_template,
    const float* __restrict__ Jreg,
    float* __restrict__ out,
    int N, long long nGroups, int nv) {
    const int bid = blockIdx.x;
    const int tid = threadIdx.x;

    // ======================= prep phase (blocks < 576) =======================
    if (bid < NJ * NSPLIT) {
        const int j  = bid / NSPLIT;
        const int sp = bid % NSPLIT;
        const int chunk = (nv + NSPLIT - 1) / NSPLIT;
        const int v0 = sp * chunk;
        const int v1 = min(nv, v0 + chunk);

        float acc[NACC];
#pragma unroll
        for (int k = 0; k < NACC; k++) acc[k] = 0.f;

        for (int v = v0 + tid; v < v1; v += 256) {
            float w = Jreg[(size_t)j * nv + v];
            acc[0] += w * v_template[v * 3 + 0];
            acc[1] += w * v_template[v * 3 + 1];
            acc[2] += w * v_template[v * 3 + 2];
            const float* sd = shapedirs + (size_t)v * 30;
#pragma unroll
            for (int m = 0; m < 30; m++) acc[3 + m] += w * sd[m];
        }

        __shared__ float red[8][NACC];
        int lane = tid & 31, warp = tid >> 5;
#pragma unroll
        for (int k = 0; k < NACC; k++) {
            float x = acc[k];
#pragma unroll
            for (int off = 16; off > 0; off >>= 1)
                x += __shfl_down_sync(0xffffffffu, x, off);
            if (lane == 0) red[warp][k] = x;
        }
        __syncthreads();
        if (tid < NACC) {
            float s = 0.f;
#pragma unroll
            for (int w = 0; w < 8; w++) s += red[w][tid];
            g_partial[bid * NACC + tid] = s;
        }
        __syncthreads();

        __shared__ int s_last;
        if (tid == 0) {
            __threadfence();
            s_last = (atomicAdd(&g_ctr, 1) == NJ * NSPLIT - 1);
        }
        __syncthreads();

        if (s_last) {
            // ---------------- finisher: reduce partials, build A ----------------
            __shared__ float sP[NJ][NACC];
            for (int i = tid; i < NJ * NACC; i += 256) {
                int jj = i / NACC, c = i % NACC;
                float s = 0.f;
#pragma unroll
                for (int sp2 = 0; sp2 < NSPLIT; sp2++)
                    s += __ldcg(&g_partial[(jj * NSPLIT + sp2) * NACC + c]);
                sP[jj][c] = s;
            }
            __syncthreads();

            __shared__ float sJ[2][NJ * 3];    // [0]=pose, [1]=da
            if (tid < NJ) {
                int jj = tid;
                float b[10];
#pragma unroll
                for (int k = 0; k < 10; k++) b[k] = __ldg(&beta[k]);
#pragma unroll
                for (int c = 0; c < 3; c++) {
                    float jd = sP[jj][c];
                    float jp = jd;
#pragma unroll
                    for (int k = 0; k < 10; k++) jp += sP[jj][3 + c * 10 + k] * b[k];
                    sJ[0][jj * 3 + c] = jp;
                    sJ[1][jj * 3 + c] = jd;
                }
            }
            __syncthreads();

            __shared__ float L[2][NJ][12];
            if (tid < 48) {
                int s = tid / NJ;          // 0 = pose, 1 = da
                int jj = tid % NJ;
                const float* th = (s == 0 ? theta : da_theta) + jj * 3;
                float rx = th[0], ry = th[1], rz = th[2];
                float nrm = sqrtf(rx * rx + ry * ry + rz * rz) + 1e-8f;
                float x = rx / nrm, y = ry / nrm, z = rz / nrm;
                float c = cosf(nrm), sn = sinf(nrm), ic = 1.0f - c;
                float* Lj = L[s][jj];
                Lj[0] = c + ic * x * x;      Lj[1] = ic * x * y - sn * z;  Lj[2] = ic * x * z + sn * y;
                Lj[3] = ic * x * y + sn * z; Lj[4] = c + ic * y * y;       Lj[5] = ic * y * z - sn * x;
                Lj[6] = ic * x * z - sn * y; Lj[7] = ic * y * z + sn * x;  Lj[8] = c + ic * z * z;
                const float* J = sJ[s];
                int p = c_par[jj];
                if (p < 0) {
                    Lj[9] = J[0]; Lj[10] = J[1]; Lj[11] = J[2];
                } else {
                    Lj[9]  = J[jj * 3 + 0] - J[p * 3 + 0];
                    Lj[10] = J[jj * 3 + 1] - J[p * 3 + 1];
                    Lj[11] = J[jj * 3 + 2] - J[p * 3 + 2];
                }
            }
            __syncthreads();

            __shared__ float sAf[NJ][12];
            if (tid < NJ) {
                int jj = tid;
                float P[12], D[12];
                chain(L[0], jj, P);
                chain(L[1], jj, D);
#pragma unroll
                for (int rr = 0; rr < 3; rr++) {
                    P[9 + rr] -= P[rr * 3 + 0] * sJ[0][jj * 3 + 0] +
                                 P[rr * 3 + 1] * sJ[0][jj * 3 + 1] +
                                 P[rr * 3 + 2] * sJ[0][jj * 3 + 2];
                    D[9 + rr] -= D[rr * 3 + 0] * sJ[1][jj * 3 + 0] +
                                 D[rr * 3 + 1] * sJ[1][jj * 3 + 1] +
                                 D[rr * 3 + 2] * sJ[1][jj * 3 + 2];
                }
                float ti[3];
#pragma unroll
                for (int rr = 0; rr < 3; rr++)
                    ti[rr] = -(D[0 * 3 + rr] * D[9] + D[1 * 3 + rr] * D[10] +
                               D[2 * 3 + rr] * D[11]);
#pragma unroll
                for (int rr = 0; rr < 3; rr++) {
#pragma unroll
                    for (int cc = 0; cc < 3; cc++)
                        sAf[jj][rr * 4 + cc] = P[rr * 3 + 0] * D[cc * 3 + 0] +
                                               P[rr * 3 + 1] * D[cc * 3 + 1] +
                                               P[rr * 3 + 2] * D[cc * 3 + 2];
                    sAf[jj][rr * 4 + 3] = P[rr * 3 + 0] * ti[0] + P[rr * 3 + 1] * ti[1] +
                                          P[rr * 3 + 2] * ti[2] + P[9 + rr];
                }
            }
            __syncthreads();

            for (int i = tid; i < NJ * 12; i += 256) {
                int jj = i / 12, k = i % 12;
                float a = sAf[jj][k];
                g_A[i] = a;
                if (jj < 23) {
                    float d = a - sAf[23][k];
                    unsigned long long u = (unsigned long long)__float_as_uint(d);
                    g_Dpk[i] = u | (u << 32);
                } else {
                    unsigned long long u = (unsigned long long)__float_as_uint(a);
                    g_A23pk[k] = u | (u << 32);
                }
            }
            __syncthreads();
            if (tid == 0) {
                g_ctr = 0;                       // reset for next replay
                __threadfence();                 // publish A before flag
                *(volatile int*)&g_flag = 1;     // release
            }
        }
    }

    // ======================= wait for A (all blocks) =======================
    __shared__ int s_go;
    if (tid == 0) {
        while (*(volatile int*)&g_flag == 0) __nanosleep(128);
        s_go = 1;
    }
    __syncthreads();
    __threadfence();   // acquire: order g_Dpk reads after flag observation
    (void)s_go;

    __shared__ __align__(16) unsigned long long sD[23 * 12];
    __shared__ __align__(16) unsigned long long sA23[12];
    for (int i = tid; i < 23 * 12 + 12; i += 256) {
        if (i < 23 * 12) sD[i] = __ldcg(&g_Dpk[i]);
        else             sA23[i - 23 * 12] = __ldcg(&g_A23pk[i - 23 * 12]);
    }
    __syncthreads();

    // ======================= LBS: 4 points/thread =======================
    long long g = (long long)bid * 256 + tid;
    if (g < nGroups) {
        const ulonglong2 X = ldcs2(reinterpret_cast<const ulonglong2*>(points) + g);
        const ulonglong2 Y = ldcs2(reinterpret_cast<const ulonglong2*>(points + (size_t)N) + g);
        const ulonglong2 Z = ldcs2(reinterpret_cast<const ulonglong2*>(points + 2 * (size_t)N) + g);

        unsigned long long vxa = 0ull, vya = 0ull, vza = 0ull;
        unsigned long long vxb = 0ull, vyb = 0ull, vzb = 0ull;

#pragma unroll
        for (int j = 0; j < 23; j++) {
            const ulonglong2 W =
                ldcs2(reinterpret_cast<const ulonglong2*>(weights + (size_t)j * N) + g);
            const ulonglong2* ap = reinterpret_cast<const ulonglong2*>(&sD[j * 12]);
            const ulonglong2 a01 = ap[0], a23_ = ap[1], a45 = ap[2];
            const ulonglong2 a67 = ap[3], a89 = ap[4], aAB = ap[5];
            unsigned long long s;
            s = fma2(a01.x, X.x, a23_.y); s = fma2(a01.y, Y.x, s); s = fma2(a23_.x, Z.x, s); vxa = fma2(W.x, s, vxa);
            s = fma2(a45.x, X.x, a67.y);  s = fma2(a45.y, Y.x, s); s = fma2(a67.x,  Z.x, s); vya = fma2(W.x, s, vya);
            s = fma2(a89.x, X.x, aAB.y);  s = fma2(a89.y, Y.x, s); s = fma2(aAB.x,  Z.x, s); vza = fma2(W.x, s, vza);
            s = fma2(a01.x, X.y, a23_.y); s = fma2(a01.y, Y.y, s); s = fma2(a23_.x, Z.y, s); vxb = fma2(W.y, s, vxb);
            s = fma2(a45.x, X.y, a67.y);  s = fma2(a45.y, Y.y, s); s = fma2(a67.x,  Z.y, s); vyb = fma2(W.y, s, vyb);
            s = fma2(a89.x, X.y, aAB.y);  s = fma2(a89.y, Y.y, s); s = fma2(aAB.x,  Z.y, s); vzb = fma2(W.y, s, vzb);
        }

        {
            const ulonglong2* ap = reinterpret_cast<const ulonglong2*>(sA23);
            const ulonglong2 a01 = ap[0], a23_ = ap[1], a45 = ap[2];
            const ulonglong2 a67 = ap[3], a89 = ap[4], aAB = ap[5];
            unsigned long long s;
            s = fma2(a01.x, X.x, a23_.y); s = fma2(a01.y, Y.x, s); s = fma2(a23_.x, Z.x, s); vxa = add2(vxa, s);
            s = fma2(a45.x, X.x, a67.y);  s = fma2(a45.y, Y.x, s); s = fma2(a67.x,  Z.x, s); vya = add2(vya, s);
            s = fma2(a89.x, X.x, aAB.y);  s = fma2(a89.y, Y.x, s); s = fma2(aAB.x,  Z.x, s); vza = add2(vza, s);
            s = fma2(a01.x, X.y, a23_.y); s = fma2(a01.y, Y.y, s); s = fma2(a23_.x, Z.y, s); vxb = add2(vxb, s);
            s = fma2(a45.x, X.y, a67.y);  s = fma2(a45.y, Y.y, s); s = fma2(a67.x,  Z.y, s); vyb = add2(vyb, s);
            s = fma2(a89.x, X.y, aAB.y);  s = fma2(a89.y, Y.y, s); s = fma2(aAB.x,  Z.y, s); vzb = add2(vzb, s);
        }

        ulonglong2 o;
        o.x = vxa; o.y = vxb; stcs2(reinterpret_cast<ulonglong2*>(out) + g, o);
        o.x = vya; o.y = vyb; stcs2(reinterpret_cast<ulonglong2*>(out + (size_t)N) + g, o);
        o.x = vza; o.y = vzb; stcs2(reinterpret_cast<ulonglong2*>(out + 2 * (size_t)N) + g, o);
    }

    // ======================= reset for next replay =======================
    if (tid == 0) {
        __threadfence();
        if (atomicAdd(&g_done, 1) == (int)gridDim.x - 1) {
            *(volatile int*)&g_flag = 0;
            g_done = 0;
        }
    }
}

// ---------------------------------------------------------------------------
// Fallback path (N % 4 != 0): plain two-kernel prep + scalar LBS.
// ---------------------------------------------------------------------------
__global__ void __launch_bounds__(256) k_prep_fb(
    const float* __restrict__ Jreg, const float* __restrict__ v_template,
    const float* __restrict__ shapedirs, const float* __restrict__ beta,
    const float* __restrict__ theta, const float* __restrict__ da_theta,
    int nv) {
    // single block, serial but correct (fallback only)
    const int tid = threadIdx.x;
    __shared__ float sJ[2][NJ * 3];
    if (tid < NJ * 2) {
        int s = tid / NJ, j = tid % NJ;
        float j0 = 0, j1 = 0, j2 = 0;
        for (int v = 0; v < nv; v++) {
            float w = Jreg[(size_t)j * nv + v];
            float t0 = v_template[v * 3 + 0], t1 = v_template[v * 3 + 1],
                  t2 = v_template[v * 3 + 2];
            if (s == 0) {
                const float* sd = shapedirs + (size_t)v * 30;
                for (int k = 0; k < 10; k++) {
                    float b = beta[k];
                    t0 += sd[k] * b; t1 += sd[10 + k] * b; t2 += sd[20 + k] * b;
                }
            }
            j0 += w * t0; j1 += w * t1; j2 += w * t2;
        }
        sJ[s][j * 3 + 0] = j0; sJ[s][j * 3 + 1] = j1; sJ[s][j * 3 + 2] = j2;
    }
    __syncthreads();
    __shared__ float L[2][NJ][12];
    if (tid < 48) {
        int s = tid / NJ, jj = tid % NJ;
        const float* th = (s == 0 ? theta : da_theta) + jj * 3;
        float rx = th[0], ry = th[1], rz = th[2];
        float nrm = sqrtf(rx * rx + ry * ry + rz * rz) + 1e-8f;
        float x = rx / nrm, y = ry / nrm, z = rz / nrm;
        float c = cosf(nrm), sn = sinf(nrm), ic = 1.0f - c;
        float* Lj = L[s][jj];
        Lj[0] = c + ic * x * x;      Lj[1] = ic * x * y - sn * z;  Lj[2] = ic * x * z + sn * y;
        Lj[3] = ic * x * y + sn * z; Lj[4] = c + ic * y * y;       Lj[5] = ic * y * z - sn * x;
        Lj[6] = ic * x * z - sn * y; Lj[7] = ic * y * z + sn * x;  Lj[8] = c + ic * z * z;
        const float* J = sJ[s];
        int p = c_par[jj];
        if (p < 0) { Lj[9] = J[0]; Lj[10] = J[1]; Lj[11] = J[2]; }
        else {
            Lj[9]  = J[jj * 3 + 0] - J[p * 3 + 0];
            Lj[10] = J[jj * 3 + 1] - J[p * 3 + 1];
            Lj[11] = J[jj * 3 + 2] - J[p * 3 + 2];
        }
    }
    __syncthreads();
    if (tid < NJ) {
        int jj = tid;
        float P[12], D[12];
        chain(L[0], jj, P);
        chain(L[1], jj, D);
        for (int rr = 0; rr < 3; rr++) {
            P[9 + rr] -= P[rr * 3 + 0] * sJ[0][jj * 3 + 0] +
                         P[rr * 3 + 1] * sJ[0][jj * 3 + 1] +
                         P[rr * 3 + 2] * sJ[0][jj * 3 + 2];
            D[9 + rr] -= D[rr * 3 + 0] * sJ[1][jj * 3 + 0] +
                         D[rr * 3 + 1] * sJ[1][jj * 3 + 1] +
                         D[rr * 3 + 2] * sJ[1][jj * 3 + 2];
        }
        float ti[3];
        for (int rr = 0; rr < 3; rr++)
            ti[rr] = -(D[0 * 3 + rr] * D[9] + D[1 * 3 + rr] * D[10] +
                       D[2 * 3 + rr] * D[11]);
        for (int rr = 0; rr < 3; rr++) {
            for (int cc = 0; cc < 3; cc++)
                g_A[jj * 12 + rr * 4 + cc] = P[rr * 3 + 0] * D[cc * 3 + 0] +
                                             P[rr * 3 + 1] * D[cc * 3 + 1] +
                                             P[rr * 3 + 2] * D[cc * 3 + 2];
            g_A[jj * 12 + rr * 4 + 3] = P[rr * 3 + 0] * ti[0] +
                                        P[rr * 3 + 1] * ti[1] +
                                        P[rr * 3 + 2] * ti[2] + P[9 + rr];
        }
    }
}

__global__ void k_lbs_scalar(const float* __restrict__ points,
                             const float* __restrict__ weights,
                             float* __restrict__ out, int N) {
    __shared__ float sA[NJ * 12];
    for (int i = threadIdx.x; i < NJ * 12; i += blockDim.x) sA[i] = __ldcg(&g_A[i]);
    __syncthreads();
    long long n = (long long)blockIdx.x * blockDim.x + threadIdx.x;
    if (n >= N) return;
    float px = points[n], py = points[(size_t)N + n], pz = points[2 * (size_t)N + n];
    float vx = 0.f, vy = 0.f, vz = 0.f;
#pragma unroll
    for (int j = 0; j < NJ; j++) {
        float w = weights[(size_t)j * N + n];
        const float* a = &sA[j * 12];
        vx += w * (a[0] * px + a[1] * py + a[2]  * pz + a[3]);
        vy += w * (a[4] * px + a[5] * py + a[6]  * pz + a[7]);
        vz += w * (a[8] * px + a[9] * py + a[10] * pz + a[11]);
    }
    out[n] = vx; out[(size_t)N + n] = vy; out[2 * (size_t)N + n] = vz;
}

// ---------------------------------------------------------------------------
extern "C" void kernel_launch(void* const* d_in, const int* in_sizes, int n_in,
                              void* d_out, int out_size) {
    const float* points      = (const float*)d_in[0];
    const float* weights     = (const float*)d_in[1];
    const float* beta        = (const float*)d_in[2];
    const float* theta       = (const float*)d_in[3];
    const float* da_theta    = (const float*)d_in[4];
    const float* shapedirs   = (const float*)d_in[5];
    const float* v_template  = (const float*)d_in[6];
    const float* J_regressor = (const float*)d_in[7];

    int N  = in_sizes[0] / 3;          // number of points
    int NV = in_sizes[5] / 30;         // template vertex count

    long long nGroups = (long long)N / 4;
    int blocks = (int)((nGroups + 255) / 256);

    if ((N & 3) == 0 && blocks >= NJ * NSPLIT + 16) {
        // single fused node: prep (first wave) + LBS
        k_all<<<blocks, 256>>>(points, weights, beta, theta, da_theta,
                               shapedirs, v_template, J_regressor,
                               (float*)d_out, N, nGroups, NV);
    } else {
        k_prep_fb<<<1, 256>>>(J_regressor, v_template, shapedirs, beta,
                              theta, da_theta, NV);
        int b2 = (N + 255) / 256;
        k_lbs_scalar<<<b2, 256>>>(points, weights, (float*)d_out, N);
    }
}